// round 16
// baseline (speedup 1.0000x reference)
#include <cuda_runtime.h>
#include <cuda_bf16.h>
#include <cstdint>

#define DINLINE __device__ __forceinline__

// ---------------- problem constants ----------------
#define B_  32
#define T_  2048
#define H_  1024
#define U_  1024

// ---------------- scores kernel tiles ----------------
#define TM 128                 // t-rows per CTA
#define TN 128                 // u per n-chunk (register accumulators)
#define TK 64                  // k (=h) per smem tile
#define NCHUNKS (U_ / TN)      // 8
#define KTILES  (H_ / TK)      // 16
#define NTHREADS 512           // 16 warps: 4m x 4n, warp tile 32x32

// padded smem row stride (bytes): 64 bf16 = 128B data, +16B pad
#define AST 144
#define TSZ (128 * AST)        // 18432 bytes per tile

// two pipeline stages, 4 tiles each (Ahi, Alo, Bhi, Blo)
#define SM_AHI 0
#define SM_ALO 18432
#define SM_BHI 36864
#define SM_BLO 55296
#define SM_STAGE 73728
#define SM_QS  147456          // 128 floats
#define SM_VS  147968
#define SM_RED 148480
#define SM_TOTAL 148992

// ---------------- device scratch (no allocation allowed) ----------------
__device__ __align__(16) __nv_bfloat16 g_W2T_hi[H_ * U_];     // [u][h]
__device__ __align__(16) __nv_bfloat16 g_W2T_lo[H_ * U_];     // [u][h]
__device__ __align__(16) __nv_bfloat16 g_enc_hi[B_ * T_ * H_]; // [b*T+t][h]
__device__ __align__(16) __nv_bfloat16 g_enc_lo[B_ * T_ * H_];
__device__ float g_q[B_ * U_];                 // dec@W1 + b1 + b2
__device__ float g_scores[B_ * T_];

// ---------------- PTX helpers ----------------
DINLINE uint32_t smem_u32(const void* p) {
    uint32_t r;
    asm("{ .reg .u64 t; cvta.to.shared.u64 t, %1; cvt.u32.u64 %0, t; }"
        : "=r"(r) : "l"(p));
    return r;
}

DINLINE void cp_async16(uint32_t dst, const void* src) {
    asm volatile("cp.async.cg.shared.global [%0], [%1], 16;"
                 :: "r"(dst), "l"(src) : "memory");
}
DINLINE void cp_commit() { asm volatile("cp.async.commit_group;" ::: "memory"); }
template<int N> DINLINE void cp_wait() {
    asm volatile("cp.async.wait_group %0;" :: "n"(N) : "memory");
}

DINLINE void ldsm_x4(uint32_t& r0, uint32_t& r1, uint32_t& r2, uint32_t& r3,
                     uint32_t addr) {
    asm volatile("ldmatrix.sync.aligned.m8n8.x4.shared.b16 {%0,%1,%2,%3}, [%4];"
                 : "=r"(r0), "=r"(r1), "=r"(r2), "=r"(r3) : "r"(addr));
}
// B stored [n][k], k contiguous: non-trans ldmatrix delivers the m16n8k16
// B fragment (thread t holds n=t>>2, k=(t&3)*2,+1) directly.
DINLINE void ldsm_x2(uint32_t& r0, uint32_t& r1, uint32_t addr) {
    asm volatile("ldmatrix.sync.aligned.m8n8.x2.shared.b16 {%0,%1}, [%2];"
                 : "=r"(r0), "=r"(r1) : "r"(addr));
}
DINLINE void mma_bf16(float& c0, float& c1, float& c2, float& c3,
                      uint32_t a0, uint32_t a1, uint32_t a2, uint32_t a3,
                      uint32_t b0, uint32_t b1) {
    asm volatile(
        "mma.sync.aligned.m16n8k16.row.col.f32.bf16.bf16.f32 "
        "{%0,%1,%2,%3}, {%4,%5,%6,%7}, {%8,%9}, {%0,%1,%2,%3};"
        : "+f"(c0), "+f"(c1), "+f"(c2), "+f"(c3)
        : "r"(a0), "r"(a1), "r"(a2), "r"(a3), "r"(b0), "r"(b1));
}

// ====================================================================
// K_pre_a: W2 [H,U] fp32 -> W2T hi/lo [U,H] bf16 split (transposed)
// ====================================================================
__global__ void w2_prep_kernel(const float* __restrict__ W2) {
    int idx = blockIdx.x * blockDim.x + threadIdx.x;
    if (idx >= H_ * U_) return;
    int h = idx / U_;
    int u = idx - h * U_;
    float x = W2[idx];
    __nv_bfloat16 hi = __float2bfloat16(x);
    __nv_bfloat16 lo = __float2bfloat16(x - __bfloat162float(hi));
    g_W2T_hi[u * H_ + h] = hi;
    g_W2T_lo[u * H_ + h] = lo;
}

// ====================================================================
// K_pre_b: enc fp32 -> bf16 hi/lo split (same layout), vectorized
// ====================================================================
__global__ void enc_prep_kernel(const float* __restrict__ enc) {
    size_t idx = (size_t)blockIdx.x * blockDim.x + threadIdx.x; // float4 slots
    const float4* src = (const float4*)enc;
    float4 v = src[idx];
    __nv_bfloat16 h0 = __float2bfloat16(v.x);
    __nv_bfloat16 h1 = __float2bfloat16(v.y);
    __nv_bfloat16 h2 = __float2bfloat16(v.z);
    __nv_bfloat16 h3 = __float2bfloat16(v.w);
    __nv_bfloat162 hp0 = __halves2bfloat162(h0, h1);
    __nv_bfloat162 hp1 = __halves2bfloat162(h2, h3);
    __nv_bfloat162 lp0 = __halves2bfloat162(
        __float2bfloat16(v.x - __bfloat162float(h0)),
        __float2bfloat16(v.y - __bfloat162float(h1)));
    __nv_bfloat162 lp1 = __halves2bfloat162(
        __float2bfloat16(v.z - __bfloat162float(h2)),
        __float2bfloat16(v.w - __bfloat162float(h3)));
    ((__nv_bfloat162*)g_enc_hi)[idx * 2]     = hp0;
    ((__nv_bfloat162*)g_enc_hi)[idx * 2 + 1] = hp1;
    ((__nv_bfloat162*)g_enc_lo)[idx * 2]     = lp0;
    ((__nv_bfloat162*)g_enc_lo)[idx * 2 + 1] = lp1;
}

// ====================================================================
// K0: q[b,u] = dec[b,:]·W1[:,u] + b1[u] + b2[u]
// ====================================================================
__global__ void q_kernel(const float* __restrict__ dec,
                         const float* __restrict__ W1,
                         const float* __restrict__ b1,
                         const float* __restrict__ b2) {
    int b = blockIdx.x;
    int u = blockIdx.y * 128 + threadIdx.x;
    const float* drow = dec + b * H_;
    float acc = b1[u] + b2[u];
#pragma unroll 4
    for (int h = 0; h < H_; h++)
        acc += drow[h] * W1[h * U_ + u];
    g_q[b * U_ + u] = acc;
}

// ====================================================================
// K1: scores[b,t] = sum_u V[u] * tanh(q[b,u] + enc[b,t,:]·W2[:,u])
//     bf16x3 split mma.sync GEMM, cp.async double-buffered,
//     16 warps (4 per SMSP) for HMMA latency hiding.
// ====================================================================
DINLINE void stage_load(uint32_t sbase, int tid,
                        const __nv_bfloat16* encHi_row,
                        const __nv_bfloat16* encLo_row,
                        int u0, int k0) {
#pragma unroll
    for (int i = 0; i < 2; i++) {
        int id = tid + i * NTHREADS;     // 1024 chunks per tile
        int r  = id >> 3;                // 0..127
        int c8 = id & 7;                 // 16B (8 bf16) column
        uint32_t off = (uint32_t)(r * AST + c8 * 16);
        size_t gofs = (size_t)r * H_ + k0 + c8 * 8;
        cp_async16(sbase + SM_AHI + off, encHi_row + gofs);
        cp_async16(sbase + SM_ALO + off, encLo_row + gofs);
        size_t wofs = (size_t)(u0 + r) * H_ + k0 + c8 * 8;
        cp_async16(sbase + SM_BHI + off, g_W2T_hi + wofs);
        cp_async16(sbase + SM_BLO + off, g_W2T_lo + wofs);
    }
}

__global__ __launch_bounds__(NTHREADS, 1)
void scores_kernel(const float* __restrict__ Vp) {
    extern __shared__ char smem[];
    uint32_t sb = smem_u32(smem);
    int tid  = threadIdx.x;
    int wid  = tid >> 5;
    int lane = tid & 31;
    int wm   = wid & 3;        // 4 m-tiles of 32
    int wn   = wid >> 2;       // 4 n-tiles of 32
    int b    = blockIdx.x >> 4;
    int t0   = (blockIdx.x & 15) * TM;

    const __nv_bfloat16* encHi_row = g_enc_hi + (size_t)(b * T_ + t0) * H_;
    const __nv_bfloat16* encLo_row = g_enc_lo + (size_t)(b * T_ + t0) * H_;

    float* qs  = (float*)(smem + SM_QS);
    float* vs  = (float*)(smem + SM_VS);
    float* red = (float*)(smem + SM_RED);
    if (tid < 128) red[tid] = 0.0f;

    // ldmatrix per-lane base offsets
    // A (m16k16, x4): row = mbase + (lane&15), 16B-block = lane>>4
    uint32_t aOff = (uint32_t)((wm * 32 + (lane & 15)) * AST + (lane >> 4) * 16);
    // B (k16n8, x2 non-trans): row n = nbase + (lane&7), 16B-block = (lane>>3)&1
    uint32_t bOff = (uint32_t)((wn * 32 + (lane & 7)) * AST + ((lane >> 3) & 1) * 16);

    float rowacc[2][2];
#pragma unroll
    for (int mi = 0; mi < 2; mi++) { rowacc[mi][0] = 0.f; rowacc[mi][1] = 0.f; }

#pragma unroll 1
    for (int nc = 0; nc < NCHUNKS; nc++) {
        int u0 = nc * TN;
        if (tid < 128) {
            qs[tid] = g_q[b * U_ + u0 + tid];
            vs[tid] = Vp[u0 + tid];
        }

        float acc[2][4][4];   // [mi][ni][reg]
#pragma unroll
        for (int mi = 0; mi < 2; mi++)
#pragma unroll
            for (int ni = 0; ni < 4; ni++)
#pragma unroll
                for (int r = 0; r < 4; r++)
                    acc[mi][ni][r] = 0.0f;

        // pipeline prologue: stage 0 <- kt 0
        stage_load(sb, tid, encHi_row, encLo_row, u0, 0);
        cp_commit();

#pragma unroll 1
        for (int kt = 0; kt < KTILES; kt++) {
            int s = kt & 1;
            if (kt + 1 < KTILES) {
                stage_load(sb + (s ^ 1) * SM_STAGE, tid, encHi_row, encLo_row,
                           u0, (kt + 1) * TK);
                cp_commit();
                cp_wait<1>();      // stage s complete; next stage may be in flight
            } else {
                cp_wait<0>();
            }
            __syncthreads();

            uint32_t sA = sb + s * SM_STAGE;
            // ---- 4 k16 steps, 3 split products each
#pragma unroll
            for (int ks = 0; ks < 4; ks++) {
                uint32_t kb = (uint32_t)(ks * 32);
                uint32_t ah[2][4], al[2][4], bh[4][2], bl[4][2];
#pragma unroll
                for (int mi = 0; mi < 2; mi++)
                    ldsm_x4(ah[mi][0], ah[mi][1], ah[mi][2], ah[mi][3],
                            sA + SM_AHI + aOff + mi * (16 * AST) + kb);
#pragma unroll
                for (int ni = 0; ni < 4; ni++)
                    ldsm_x2(bh[ni][0], bh[ni][1],
                            sA + SM_BHI + bOff + ni * (8 * AST) + kb);
#pragma unroll
                for (int mi = 0; mi < 2; mi++)
#pragma unroll
                    for (int ni = 0; ni < 4; ni++)
                        mma_bf16(acc[mi][ni][0], acc[mi][ni][1],
                                 acc[mi][ni][2], acc[mi][ni][3],
                                 ah[mi][0], ah[mi][1], ah[mi][2], ah[mi][3],
                                 bh[ni][0], bh[ni][1]);
#pragma unroll
                for (int mi = 0; mi < 2; mi++)
                    ldsm_x4(al[mi][0], al[mi][1], al[mi][2], al[mi][3],
                            sA + SM_ALO + aOff + mi * (16 * AST) + kb);
#pragma unroll
                for (int mi = 0; mi < 2; mi++)
#pragma unroll
                    for (int ni = 0; ni < 4; ni++)
                        mma_bf16(acc[mi][ni][0], acc[mi][ni][1],
                                 acc[mi][ni][2], acc[mi][ni][3],
                                 al[mi][0], al[mi][1], al[mi][2], al[mi][3],
                                 bh[ni][0], bh[ni][1]);
#pragma unroll
                for (int ni = 0; ni < 4; ni++)
                    ldsm_x2(bl[ni][0], bl[ni][1],
                            sA + SM_BLO + bOff + ni * (8 * AST) + kb);
#pragma unroll
                for (int mi = 0; mi < 2; mi++)
#pragma unroll
                    for (int ni = 0; ni < 4; ni++)
                        mma_bf16(acc[mi][ni][0], acc[mi][ni][1],
                                 acc[mi][ni][2], acc[mi][ni][3],
                                 ah[mi][0], ah[mi][1], ah[mi][2], ah[mi][3],
                                 bl[ni][0], bl[ni][1]);
            }
            __syncthreads();   // all warps done reading stage s before reuse
        }

        // ---- epilogue: tanh(D + q)·V, accumulate per-row partials
#pragma unroll
        for (int mi = 0; mi < 2; mi++) {
#pragma unroll
            for (int ni = 0; ni < 4; ni++) {
                int uc = wn * 32 + ni * 8 + (lane & 3) * 2;
                float q0 = qs[uc], q1 = qs[uc + 1];
                float v0 = vs[uc], v1 = vs[uc + 1];
                rowacc[mi][0] += tanhf(acc[mi][ni][0] + q0) * v0
                               + tanhf(acc[mi][ni][1] + q1) * v1;
                rowacc[mi][1] += tanhf(acc[mi][ni][2] + q0) * v0
                               + tanhf(acc[mi][ni][3] + q1) * v1;
            }
        }
        __syncthreads();   // qs/vs reads done before next chunk overwrites
    }

    // reduce across the 4 lanes sharing a row, then across the 4 wn warps
#pragma unroll
    for (int mi = 0; mi < 2; mi++) {
#pragma unroll
        for (int j = 0; j < 2; j++) {
            rowacc[mi][j] += __shfl_xor_sync(0xffffffffu, rowacc[mi][j], 1);
            rowacc[mi][j] += __shfl_xor_sync(0xffffffffu, rowacc[mi][j], 2);
        }
    }
    if ((lane & 3) == 0) {
        int r0 = wm * 32 + (lane >> 2);
#pragma unroll
        for (int mi = 0; mi < 2; mi++) {
            atomicAdd(&red[r0 + mi * 16],     rowacc[mi][0]);
            atomicAdd(&red[r0 + mi * 16 + 8], rowacc[mi][1]);
        }
    }
    __syncthreads();
    if (tid < 128)
        g_scores[b * T_ + t0 + tid] = red[tid];
}

// ====================================================================
// K2: softmax over T per batch  -> attn at out + B_*H_
// ====================================================================
__global__ void softmax_kernel(float* __restrict__ out) {
    int b = blockIdx.x;
    int tid = threadIdx.x;
    __shared__ float red[256];

    float v[8];
    float m = -1e30f;
#pragma unroll
    for (int i = 0; i < 8; i++) {
        v[i] = g_scores[b * T_ + tid + i * 256];
        m = fmaxf(m, v[i]);
    }
    red[tid] = m; __syncthreads();
    for (int s = 128; s > 0; s >>= 1) {
        if (tid < s) red[tid] = fmaxf(red[tid], red[tid + s]);
        __syncthreads();
    }
    m = red[0]; __syncthreads();

    float sum = 0.0f;
#pragma unroll
    for (int i = 0; i < 8; i++) { v[i] = expf(v[i] - m); sum += v[i]; }
    red[tid] = sum; __syncthreads();
    for (int s = 128; s > 0; s >>= 1) {
        if (tid < s) red[tid] += red[tid + s];
        __syncthreads();
    }
    float inv = 1.0f / red[0];

    float* attn = out + B_ * H_;
#pragma unroll
    for (int i = 0; i < 8; i++)
        attn[b * T_ + tid + i * 256] = v[i] * inv;
}

// ====================================================================
// K3: context[b,h] = sum_t attn[b,t] * enc[b,t,h]
// ====================================================================
__global__ __launch_bounds__(512)
void context_kernel(const float* __restrict__ enc, float* __restrict__ out) {
    int b = blockIdx.x;
    int c = blockIdx.y;                 // 8 column chunks of 128
    int tid = threadIdx.x;
    int h  = c * 128 + (tid & 127);
    int tp = tid >> 7;                  // 0..3 t-partition
    const float* attn = out + B_ * H_ + b * T_;
    const float* ep   = enc + (size_t)b * T_ * H_ + h;

    float acc = 0.0f;
#pragma unroll 4
    for (int t = tp; t < T_; t += 4)
        acc += attn[t] * ep[(size_t)t * H_];

    __shared__ float red[512];
    red[tid] = acc; __syncthreads();
    if (tid < 128)
        out[b * H_ + c * 128 + tid] =
            red[tid] + red[tid + 128] + red[tid + 256] + red[tid + 384];
}

// ====================================================================
// launch
// ====================================================================
extern "C" void kernel_launch(void* const* d_in, const int* in_sizes, int n_in,
                              void* d_out, int out_size) {
    const float* dec = (const float*)d_in[0];
    const float* enc = (const float*)d_in[1];
    const float* W1  = (const float*)d_in[2];
    const float* b1  = (const float*)d_in[3];
    const float* W2  = (const float*)d_in[4];
    const float* b2  = (const float*)d_in[5];
    const float* Vp  = (const float*)d_in[6];
    // d_in[7] = bv: softmax is shift-invariant and the raw score is not an
    // output, so bv cancels exactly — intentionally unused.
    float* out = (float*)d_out;

    cudaFuncSetAttribute(scores_kernel,
                         cudaFuncAttributeMaxDynamicSharedMemorySize, SM_TOTAL);

    w2_prep_kernel<<<(H_ * U_ + 255) / 256, 256>>>(W2);
    enc_prep_kernel<<<(B_ * T_ * H_ / 4) / 256, 256>>>(enc);
    q_kernel<<<dim3(B_, U_ / 128), 128>>>(dec, W1, b1, b2);
    scores_kernel<<<B_ * (T_ / TM), NTHREADS, SM_TOTAL>>>(Vp);
    softmax_kernel<<<B_, 256>>>(out);
    context_kernel<<<dim3(B_, H_ / 128), 512>>>(enc, out);
}

// round 17
// speedup vs baseline: 1.0375x; 1.0375x over previous
#include <cuda_runtime.h>
#include <cuda_bf16.h>
#include <cstdint>

#define DINLINE __device__ __forceinline__

// ---------------- problem constants ----------------
#define B_  32
#define T_  2048
#define H_  1024
#define U_  1024

// ---------------- scores kernel tiles ----------------
#define TM 128                 // t-rows per CTA
#define TN 128                 // u per n-chunk (register accumulators)
#define TK 64                  // k (=h) per smem tile
#define NCHUNKS (U_ / TN)      // 8
#define KTILES  (H_ / TK)      // 16
#define NITER   (NCHUNKS * KTILES)   // 128 flattened pipeline steps
#define NTHREADS 512           // 16 warps: 4m x 4n, warp tile 32x32

// padded smem row stride (bytes): 64 bf16 = 128B data, +16B pad
#define AST 144

// three pipeline stages, 4 tiles each (Ahi, Alo, Bhi, Blo)
#define SM_AHI 0
#define SM_ALO 18432
#define SM_BHI 36864
#define SM_BLO 55296
#define SM_STAGE 73728
#define SM_QS  221184          // 128 floats
#define SM_VS  221696
#define SM_RED 222208
#define SM_TOTAL 222720

// ---------------- device scratch (no allocation allowed) ----------------
__device__ __align__(16) __nv_bfloat16 g_W2T_hi[H_ * U_];     // [u][h]
__device__ __align__(16) __nv_bfloat16 g_W2T_lo[H_ * U_];     // [u][h]
__device__ __align__(16) __nv_bfloat16 g_enc_hi[B_ * T_ * H_]; // [b*T+t][h]
__device__ __align__(16) __nv_bfloat16 g_enc_lo[B_ * T_ * H_];
__device__ float g_q[B_ * U_];                 // dec@W1 + b1 + b2
__device__ float g_scores[B_ * T_];

// ---------------- PTX helpers ----------------
DINLINE uint32_t smem_u32(const void* p) {
    uint32_t r;
    asm("{ .reg .u64 t; cvta.to.shared.u64 t, %1; cvt.u32.u64 %0, t; }"
        : "=r"(r) : "l"(p));
    return r;
}

DINLINE void cp_async16(uint32_t dst, const void* src) {
    asm volatile("cp.async.cg.shared.global [%0], [%1], 16;"
                 :: "r"(dst), "l"(src) : "memory");
}
DINLINE void cp_commit() { asm volatile("cp.async.commit_group;" ::: "memory"); }
template<int N> DINLINE void cp_wait() {
    asm volatile("cp.async.wait_group %0;" :: "n"(N) : "memory");
}

DINLINE void ldsm_x4(uint32_t& r0, uint32_t& r1, uint32_t& r2, uint32_t& r3,
                     uint32_t addr) {
    asm volatile("ldmatrix.sync.aligned.m8n8.x4.shared.b16 {%0,%1,%2,%3}, [%4];"
                 : "=r"(r0), "=r"(r1), "=r"(r2), "=r"(r3) : "r"(addr));
}
DINLINE void mma_bf16(float& c0, float& c1, float& c2, float& c3,
                      uint32_t a0, uint32_t a1, uint32_t a2, uint32_t a3,
                      uint32_t b0, uint32_t b1) {
    asm volatile(
        "mma.sync.aligned.m16n8k16.row.col.f32.bf16.bf16.f32 "
        "{%0,%1,%2,%3}, {%4,%5,%6,%7}, {%8,%9}, {%0,%1,%2,%3};"
        : "+f"(c0), "+f"(c1), "+f"(c2), "+f"(c3)
        : "r"(a0), "r"(a1), "r"(a2), "r"(a3), "r"(b0), "r"(b1));
}

// ====================================================================
// K_pre_a: W2 [H,U] fp32 -> W2T hi/lo [U,H] bf16 split (transposed)
// ====================================================================
__global__ void w2_prep_kernel(const float* __restrict__ W2) {
    int idx = blockIdx.x * blockDim.x + threadIdx.x;
    if (idx >= H_ * U_) return;
    int h = idx / U_;
    int u = idx - h * U_;
    float x = W2[idx];
    __nv_bfloat16 hi = __float2bfloat16(x);
    __nv_bfloat16 lo = __float2bfloat16(x - __bfloat162float(hi));
    g_W2T_hi[u * H_ + h] = hi;
    g_W2T_lo[u * H_ + h] = lo;
}

// ====================================================================
// K_pre_b: enc fp32 -> bf16 hi/lo split (same layout), vectorized
// ====================================================================
__global__ void enc_prep_kernel(const float* __restrict__ enc) {
    size_t idx = (size_t)blockIdx.x * blockDim.x + threadIdx.x; // float4 slots
    const float4* src = (const float4*)enc;
    float4 v = src[idx];
    __nv_bfloat16 h0 = __float2bfloat16(v.x);
    __nv_bfloat16 h1 = __float2bfloat16(v.y);
    __nv_bfloat16 h2 = __float2bfloat16(v.z);
    __nv_bfloat16 h3 = __float2bfloat16(v.w);
    __nv_bfloat162 hp0 = __halves2bfloat162(h0, h1);
    __nv_bfloat162 hp1 = __halves2bfloat162(h2, h3);
    __nv_bfloat162 lp0 = __halves2bfloat162(
        __float2bfloat16(v.x - __bfloat162float(h0)),
        __float2bfloat16(v.y - __bfloat162float(h1)));
    __nv_bfloat162 lp1 = __halves2bfloat162(
        __float2bfloat16(v.z - __bfloat162float(h2)),
        __float2bfloat16(v.w - __bfloat162float(h3)));
    ((__nv_bfloat162*)g_enc_hi)[idx * 2]     = hp0;
    ((__nv_bfloat162*)g_enc_hi)[idx * 2 + 1] = hp1;
    ((__nv_bfloat162*)g_enc_lo)[idx * 2]     = lp0;
    ((__nv_bfloat162*)g_enc_lo)[idx * 2 + 1] = lp1;
}

// ====================================================================
// K0: q[b,u] = dec[b,:]·W1[:,u] + b1[u] + b2[u]
// ====================================================================
__global__ void q_kernel(const float* __restrict__ dec,
                         const float* __restrict__ W1,
                         const float* __restrict__ b1,
                         const float* __restrict__ b2) {
    int b = blockIdx.x;
    int u = blockIdx.y * 128 + threadIdx.x;
    const float* drow = dec + b * H_;
    float acc = b1[u] + b2[u];
#pragma unroll 4
    for (int h = 0; h < H_; h++)
        acc += drow[h] * W1[h * U_ + u];
    g_q[b * U_ + u] = acc;
}

// ====================================================================
// K1: scores[b,t] = sum_u V[u] * tanh(q[b,u] + enc[b,t,:]·W2[:,u])
//     bf16x3 split mma.sync GEMM, flattened 3-stage cp.async pipeline,
//     one barrier per k-tile, x4 ldmatrix for both operands.
// ====================================================================
DINLINE void stage_load(uint32_t sbase, int tid,
                        const __nv_bfloat16* encHi_row,
                        const __nv_bfloat16* encLo_row,
                        int u0, int k0) {
#pragma unroll
    for (int i = 0; i < 2; i++) {
        int id = tid + i * NTHREADS;     // 1024 chunks per tile
        int r  = id >> 3;                // 0..127
        int c8 = id & 7;                 // 16B (8 bf16) column
        uint32_t off = (uint32_t)(r * AST + c8 * 16);
        size_t gofs = (size_t)r * H_ + k0 + c8 * 8;
        cp_async16(sbase + SM_AHI + off, encHi_row + gofs);
        cp_async16(sbase + SM_ALO + off, encLo_row + gofs);
        size_t wofs = (size_t)(u0 + r) * H_ + k0 + c8 * 8;
        cp_async16(sbase + SM_BHI + off, g_W2T_hi + wofs);
        cp_async16(sbase + SM_BLO + off, g_W2T_lo + wofs);
    }
}

__global__ __launch_bounds__(NTHREADS, 1)
void scores_kernel(const float* __restrict__ Vp) {
    extern __shared__ char smem[];
    uint32_t sb = smem_u32(smem);
    int tid  = threadIdx.x;
    int wid  = tid >> 5;
    int lane = tid & 31;
    int wm   = wid & 3;        // 4 m-tiles of 32
    int wn   = wid >> 2;       // 4 n-tiles of 32
    int b    = blockIdx.x >> 4;
    int t0   = (blockIdx.x & 15) * TM;

    const __nv_bfloat16* encHi_row = g_enc_hi + (size_t)(b * T_ + t0) * H_;
    const __nv_bfloat16* encLo_row = g_enc_lo + (size_t)(b * T_ + t0) * H_;

    float* qs  = (float*)(smem + SM_QS);
    float* vs  = (float*)(smem + SM_VS);
    float* red = (float*)(smem + SM_RED);
    if (tid < 128) red[tid] = 0.0f;

    // ldmatrix per-lane base offsets
    // A (m16k16, x4): row = mbase + (lane&15), 16B-block = lane>>4
    uint32_t aOff = (uint32_t)((wm * 32 + (lane & 15)) * AST + (lane >> 4) * 16);
    // B (x4, two n8 frags + both k-halves): lanes 0-7 -> n rows lo8 @k0,
    // 8-15 -> lo8 @k1, 16-23 -> hi8 @k0, 24-31 -> hi8 @k1
    uint32_t bOff = (uint32_t)((wn * 32 + (lane & 7) + ((lane >> 4) << 3)) * AST
                               + ((lane >> 3) & 1) * 16);

    float rowacc[2][2];
#pragma unroll
    for (int mi = 0; mi < 2; mi++) { rowacc[mi][0] = 0.f; rowacc[mi][1] = 0.f; }

    float acc[2][4][4];   // [mi][ni][reg]

    // pipeline prologue: stages 0,1 <- iters 0,1
    stage_load(sb, tid, encHi_row, encLo_row, 0, 0);
    cp_commit();
    stage_load(sb + SM_STAGE, tid, encHi_row, encLo_row, 0, TK);
    cp_commit();

#pragma unroll 1
    for (int it = 0; it < NITER; it++) {
        if (it < NITER - 1) cp_wait<1>();
        else                cp_wait<0>();
        __syncthreads();   // stage (it%3) data visible to all; prior readers of
                           // stage ((it+2)%3) (== compute of it-1) are done

        if (it + 2 < NITER) {
            int nx = it + 2;
            stage_load(sb + (nx % 3) * SM_STAGE, tid, encHi_row, encLo_row,
                       (nx >> 4) * TN, (nx & 15) * TK);
            cp_commit();
        }

        if ((it & 15) == 0) {           // new n-chunk
            int u0 = (it >> 4) * TN;
            if (tid < 128) {
                qs[tid] = g_q[b * U_ + u0 + tid];
                vs[tid] = Vp[u0 + tid];
            }
#pragma unroll
            for (int mi = 0; mi < 2; mi++)
#pragma unroll
                for (int ni = 0; ni < 4; ni++)
#pragma unroll
                    for (int r = 0; r < 4; r++)
                        acc[mi][ni][r] = 0.0f;
        }

        uint32_t sA = sb + (it % 3) * SM_STAGE;
        // ---- 4 k16 steps, 3 split products each
#pragma unroll
        for (int ks = 0; ks < 4; ks++) {
            uint32_t kb = (uint32_t)(ks * 32);
            uint32_t ah[2][4], al[2][4], bh[4][2], bl[4][2];
#pragma unroll
            for (int mi = 0; mi < 2; mi++)
                ldsm_x4(ah[mi][0], ah[mi][1], ah[mi][2], ah[mi][3],
                        sA + SM_AHI + aOff + mi * (16 * AST) + kb);
#pragma unroll
            for (int p = 0; p < 2; p++)
                ldsm_x4(bh[2*p][0], bh[2*p][1], bh[2*p+1][0], bh[2*p+1][1],
                        sA + SM_BHI + bOff + p * (16 * AST) + kb);
#pragma unroll
            for (int mi = 0; mi < 2; mi++)
#pragma unroll
                for (int ni = 0; ni < 4; ni++)
                    mma_bf16(acc[mi][ni][0], acc[mi][ni][1],
                             acc[mi][ni][2], acc[mi][ni][3],
                             ah[mi][0], ah[mi][1], ah[mi][2], ah[mi][3],
                             bh[ni][0], bh[ni][1]);
#pragma unroll
            for (int mi = 0; mi < 2; mi++)
                ldsm_x4(al[mi][0], al[mi][1], al[mi][2], al[mi][3],
                        sA + SM_ALO + aOff + mi * (16 * AST) + kb);
#pragma unroll
            for (int mi = 0; mi < 2; mi++)
#pragma unroll
                for (int ni = 0; ni < 4; ni++)
                    mma_bf16(acc[mi][ni][0], acc[mi][ni][1],
                             acc[mi][ni][2], acc[mi][ni][3],
                             al[mi][0], al[mi][1], al[mi][2], al[mi][3],
                             bh[ni][0], bh[ni][1]);
#pragma unroll
            for (int p = 0; p < 2; p++)
                ldsm_x4(bl[2*p][0], bl[2*p][1], bl[2*p+1][0], bl[2*p+1][1],
                        sA + SM_BLO + bOff + p * (16 * AST) + kb);
#pragma unroll
            for (int mi = 0; mi < 2; mi++)
#pragma unroll
                for (int ni = 0; ni < 4; ni++)
                    mma_bf16(acc[mi][ni][0], acc[mi][ni][1],
                             acc[mi][ni][2], acc[mi][ni][3],
                             ah[mi][0], ah[mi][1], ah[mi][2], ah[mi][3],
                             bl[ni][0], bl[ni][1]);
        }

        if ((it & 15) == 15) {
            // ---- epilogue: tanh(D + q)·V, accumulate per-row partials.
            // qs/vs reads here are protected from the next n-chunk's writes by
            // the __syncthreads at the top of iteration it+1.
#pragma unroll
            for (int mi = 0; mi < 2; mi++) {
#pragma unroll
                for (int ni = 0; ni < 4; ni++) {
                    int uc = wn * 32 + ni * 8 + (lane & 3) * 2;
                    float q0 = qs[uc], q1 = qs[uc + 1];
                    float v0 = vs[uc], v1 = vs[uc + 1];
                    rowacc[mi][0] += tanhf(acc[mi][ni][0] + q0) * v0
                                   + tanhf(acc[mi][ni][1] + q1) * v1;
                    rowacc[mi][1] += tanhf(acc[mi][ni][2] + q0) * v0
                                   + tanhf(acc[mi][ni][3] + q1) * v1;
                }
            }
        }
    }

    // reduce across the 4 lanes sharing a row, then across the 4 wn warps
#pragma unroll
    for (int mi = 0; mi < 2; mi++) {
#pragma unroll
        for (int j = 0; j < 2; j++) {
            rowacc[mi][j] += __shfl_xor_sync(0xffffffffu, rowacc[mi][j], 1);
            rowacc[mi][j] += __shfl_xor_sync(0xffffffffu, rowacc[mi][j], 2);
        }
    }
    __syncthreads();       // red[] zero-init + all compute done
    if ((lane & 3) == 0) {
        int r0 = wm * 32 + (lane >> 2);
#pragma unroll
        for (int mi = 0; mi < 2; mi++) {
            atomicAdd(&red[r0 + mi * 16],     rowacc[mi][0]);
            atomicAdd(&red[r0 + mi * 16 + 8], rowacc[mi][1]);
        }
    }
    __syncthreads();
    if (tid < 128)
        g_scores[b * T_ + t0 + tid] = red[tid];
}

// ====================================================================
// K2: softmax over T per batch  -> attn at out + B_*H_
// ====================================================================
__global__ void softmax_kernel(float* __restrict__ out) {
    int b = blockIdx.x;
    int tid = threadIdx.x;
    __shared__ float red[256];

    float v[8];
    float m = -1e30f;
#pragma unroll
    for (int i = 0; i < 8; i++) {
        v[i] = g_scores[b * T_ + tid + i * 256];
        m = fmaxf(m, v[i]);
    }
    red[tid] = m; __syncthreads();
    for (int s = 128; s > 0; s >>= 1) {
        if (tid < s) red[tid] = fmaxf(red[tid], red[tid + s]);
        __syncthreads();
    }
    m = red[0]; __syncthreads();

    float sum = 0.0f;
#pragma unroll
    for (int i = 0; i < 8; i++) { v[i] = expf(v[i] - m); sum += v[i]; }
    red[tid] = sum; __syncthreads();
    for (int s = 128; s > 0; s >>= 1) {
        if (tid < s) red[tid] += red[tid + s];
        __syncthreads();
    }
    float inv = 1.0f / red[0];

    float* attn = out + B_ * H_;
#pragma unroll
    for (int i = 0; i < 8; i++)
        attn[b * T_ + tid + i * 256] = v[i] * inv;
}

// ====================================================================
// K3: context[b,h] = sum_t attn[b,t] * enc[b,t,h]
// ====================================================================
__global__ __launch_bounds__(512)
void context_kernel(const float* __restrict__ enc, float* __restrict__ out) {
    int b = blockIdx.x;
    int c = blockIdx.y;                 // 8 column chunks of 128
    int tid = threadIdx.x;
    int h  = c * 128 + (tid & 127);
    int tp = tid >> 7;                  // 0..3 t-partition
    const float* attn = out + B_ * H_ + b * T_;
    const float* ep   = enc + (size_t)b * T_ * H_ + h;

    float acc = 0.0f;
#pragma unroll 4
    for (int t = tp; t < T_; t += 4)
        acc += attn[t] * ep[(size_t)t * H_];

    __shared__ float red[512];
    red[tid] = acc; __syncthreads();
    if (tid < 128)
        out[b * H_ + c * 128 + tid] =
            red[tid] + red[tid + 128] + red[tid + 256] + red[tid + 384];
}

// ====================================================================
// launch
// ====================================================================
extern "C" void kernel_launch(void* const* d_in, const int* in_sizes, int n_in,
                              void* d_out, int out_size) {
    const float* dec = (const float*)d_in[0];
    const float* enc = (const float*)d_in[1];
    const float* W1  = (const float*)d_in[2];
    const float* b1  = (const float*)d_in[3];
    const float* W2  = (const float*)d_in[4];
    const float* b2  = (const float*)d_in[5];
    const float* Vp  = (const float*)d_in[6];
    // d_in[7] = bv: softmax is shift-invariant and the raw score is not an
    // output, so bv cancels exactly — intentionally unused.
    float* out = (float*)d_out;

    cudaFuncSetAttribute(scores_kernel,
                         cudaFuncAttributeMaxDynamicSharedMemorySize, SM_TOTAL);

    w2_prep_kernel<<<(H_ * U_ + 255) / 256, 256>>>(W2);
    enc_prep_kernel<<<(B_ * T_ * H_ / 4) / 256, 256>>>(enc);
    q_kernel<<<dim3(B_, U_ / 128), 128>>>(dec, W1, b1, b2);
    scores_kernel<<<B_ * (T_ / TM), NTHREADS, SM_TOTAL>>>(Vp);
    softmax_kernel<<<B_, 256>>>(out);
    context_kernel<<<dim3(B_, H_ / 128), 512>>>(enc, out);
}